// round 7
// baseline (speedup 1.0000x reference)
#include <cuda_runtime.h>
#include <cuda_fp16.h>
#include <stdint.h>

#define N_ROWS   262144
#define TILE_M   256
#define NTHREADS 256
#define SMEM_BYTES 149504

// fp16 weights: W2 [256][128] @0, W3 [128][256] @32768, W4 [512][128] @65536
__device__ __half g_Wh[131072];

__global__ void cvt_weights_kernel(const float* __restrict__ W2,
                                   const float* __restrict__ W3,
                                   const float* __restrict__ W4) {
    int i = blockIdx.x * blockDim.x + threadIdx.x;   // 65536 threads
    if (i < 32768) {
        g_Wh[i]         = __float2half_rn(W2[i]);
        g_Wh[32768 + i] = __float2half_rn(W3[i]);
    }
    g_Wh[65536 + i] = __float2half_rn(W4[i]);
}

__device__ __forceinline__ uint32_t smem_u32(const void* p) {
    return (uint32_t)__cvta_generic_to_shared(p);
}

__device__ __forceinline__ void ldmatrix_x4(uint32_t r[4], uint32_t addr) {
    asm volatile("ldmatrix.sync.aligned.m8n8.x4.shared.b16 {%0,%1,%2,%3}, [%4];\n"
                 : "=r"(r[0]), "=r"(r[1]), "=r"(r[2]), "=r"(r[3]) : "r"(addr));
}

__device__ __forceinline__ void mma16816(float c[4], const uint32_t a[4], uint32_t b0, uint32_t b1) {
    asm volatile("mma.sync.aligned.m16n8k16.row.col.f32.f16.f16.f32 "
                 "{%0,%1,%2,%3},{%4,%5,%6,%7},{%8,%9},{%0,%1,%2,%3};\n"
                 : "+f"(c[0]), "+f"(c[1]), "+f"(c[2]), "+f"(c[3])
                 : "r"(a[0]), "r"(a[1]), "r"(a[2]), "r"(a[3]), "r"(b0), "r"(b1));
}

__device__ __forceinline__ void cp_async16(uint32_t dst_smem, const void* src) {
    asm volatile("cp.async.cg.shared.global [%0], [%1], 16;\n" :: "r"(dst_smem), "l"(src));
}
__device__ __forceinline__ void cp_commit() { asm volatile("cp.async.commit_group;\n"); }
template <int n>
__device__ __forceinline__ void cp_wait() { asm volatile("cp.async.wait_group %0;\n" :: "n"(n)); }

// tanh-GELU in sigmoid form: gelu(x) = x * sigmoid(1.5957691x + 0.0713548x^3)
__device__ __forceinline__ float fast_gelu(float x) {
    float x3 = x * x * x;
    float z  = fmaf(0.0713548162726f, x3, 1.5957691216057308f * x);
    float e  = __expf(-z);
    return __fdividef(x, 1.0f + e);
}

__device__ __forceinline__ uint32_t pack_h2(float a, float b) {
    __half2 h = __floats2half2_rn(a, b);
    return *(uint32_t*)&h;
}

// async copy fp16 weight block [nrows][kh] (dense global) into smem with row stride ld (halves)
__device__ __forceinline__ void copy_w_async(const __half* __restrict__ src, int nrows, int kh,
                                             uint32_t dst_u32, int ld, int tid) {
    int nv  = kh >> 3;            // 16B chunks per row
    int tot = nrows * nv;
    for (int i = tid; i < tot; i += NTHREADS) {
        int r = i / nv, c = (i - r * nv) << 3;
        cp_async16(dst_u32 + (uint32_t)((r * ld + c) * 2), src + r * kh + c);
    }
}

__global__ __launch_bounds__(NTHREADS, 1)
void embedder_kernel(const float* __restrict__ joint_info,
                     const int* __restrict__ joint_token,
                     const float* __restrict__ emb,
                     const float* __restrict__ W1, const float* __restrict__ b1,
                     const float* __restrict__ b2, const float* __restrict__ b3,
                     float* __restrict__ out) {
    extern __shared__ char smem[];
    // bufA @0 (69632B), bufB @69632 (69632B)
    float4* sX   = (float4*)(smem + 139264);     // 4096 B (256 rows)
    float*  sW1  = (float*)(smem + 143360);      // 2048 B
    float*  sB1  = (float*)(smem + 145408);      // 512 B
    float*  sB2  = (float*)(smem + 145920);      // 1024 B
    float*  sB3  = (float*)(smem + 146944);      // 512 B
    int*    sTok = (int*)(smem + 147456);        // 1024 B
    int*    sPad = (int*)(smem + 148480);        // 1024 B

    uint32_t bufA = smem_u32(smem);
    uint32_t bufB = bufA + 69632;

    int tid  = threadIdx.x;
    int lane = tid & 31, warp = tid >> 5;
    int R0   = blockIdx.x * TILE_M;

    // ---- plain loads of small data ----
    {
        float4 x = ((const float4*)joint_info)[R0 + tid];
        sX[tid]   = x;
        sTok[tid] = joint_token[R0 + tid];
        sPad[tid] = (x.x == 0.0f && x.y == 0.0f && x.z == 0.0f && x.w == 0.0f) ? 1 : 0;
    }
    if (tid < 128) {
        sB1[tid] = b1[tid];
        sB3[tid] = b3[tid];
    }
    sB2[tid] = b2[tid];
    ((float2*)sW1)[tid] = ((const float2*)W1)[tid];   // 512 floats of W1

    // ---- prefetch W2 -> bufA, W3 -> bufB ----
    copy_w_async(g_Wh, 256, 128, bufA, 136, tid);         // group: W2
    cp_commit();
    copy_w_async(g_Wh + 32768, 128, 256, bufB, 264, tid); // group: W3
    cp_commit();
    __syncthreads();   // sX/sW1/biases visible

    // per-lane fragment coords
    int g = lane >> 2, t = lane & 3;            // C/A fragment coords
    int mi = lane >> 3, ri = lane & 7;          // ldmatrix coords
    int wrow = ri + ((mi & 1) << 3);
    int wcol = (mi >> 1) << 3;
    int r0 = warp * 16;                         // set 0 rows [r0,r0+16), set 1 rows +128

    // ---- layer 1 (K=4) scalar fp32 -> h1 A-fragments, 2 row-sets ----
    uint32_t h1A[2][8][4];
#pragma unroll
    for (int s = 0; s < 2; ++s) {
        float4 xa = sX[s * 128 + r0 + g];
        float4 xb = sX[s * 128 + r0 + g + 8];
#pragma unroll
        for (int kt = 0; kt < 8; ++kt)
#pragma unroll
            for (int j = 0; j < 2; ++j) {
                int c0 = kt * 16 + j * 8 + t * 2;
                float4 w0 = *(const float4*)&sW1[c0 * 4];
                float4 w1 = *(const float4*)&sW1[(c0 + 1) * 4];
                float bb0 = sB1[c0], bb1 = sB1[c0 + 1];
                float ya0 = fmaf(xa.x, w0.x, fmaf(xa.y, w0.y, fmaf(xa.z, w0.z, fmaf(xa.w, w0.w, bb0))));
                float ya1 = fmaf(xa.x, w1.x, fmaf(xa.y, w1.y, fmaf(xa.z, w1.z, fmaf(xa.w, w1.w, bb1))));
                float yb0 = fmaf(xb.x, w0.x, fmaf(xb.y, w0.y, fmaf(xb.z, w0.z, fmaf(xb.w, w0.w, bb0))));
                float yb1 = fmaf(xb.x, w1.x, fmaf(xb.y, w1.y, fmaf(xb.z, w1.z, fmaf(xb.w, w1.w, bb1))));
                h1A[s][kt][2 * j + 0] = pack_h2(fast_gelu(ya0), fast_gelu(ya1));
                h1A[s][kt][2 * j + 1] = pack_h2(fast_gelu(yb0), fast_gelu(yb1));
            }
    }

    cp_wait<1>();        // W2 ready
    __syncthreads();

    // ---- layer 2: h1[2][16x128] @ W2[256x128]^T -> h2 fragments ----
    uint32_t h2A[2][16][4];
    {
        uint32_t wb = bufA + (uint32_t)((wrow * 136 + wcol) * 2);
#pragma unroll
        for (int ng = 0; ng < 16; ++ng) {
            int n0 = ng * 16;
            float c0[8] = {0, 0, 0, 0, 0, 0, 0, 0};
            float c1[8] = {0, 0, 0, 0, 0, 0, 0, 0};
#pragma unroll
            for (int kt = 0; kt < 8; ++kt) {
                uint32_t bb[4];
                ldmatrix_x4(bb, wb + (uint32_t)(n0 * 272 + kt * 32));
                mma16816(c0 + 0, h1A[0][kt], bb[0], bb[2]);
                mma16816(c0 + 4, h1A[0][kt], bb[1], bb[3]);
                mma16816(c1 + 0, h1A[1][kt], bb[0], bb[2]);
                mma16816(c1 + 4, h1A[1][kt], bb[1], bb[3]);
            }
            float b0 = sB2[n0 + 2 * t], b1v = sB2[n0 + 2 * t + 1];
            float b2v = sB2[n0 + 8 + 2 * t], b3v = sB2[n0 + 9 + 2 * t];
            h2A[0][ng][0] = pack_h2(fast_gelu(c0[0] + b0), fast_gelu(c0[1] + b1v));
            h2A[0][ng][1] = pack_h2(fast_gelu(c0[2] + b0), fast_gelu(c0[3] + b1v));
            h2A[0][ng][2] = pack_h2(fast_gelu(c0[4] + b2v), fast_gelu(c0[5] + b3v));
            h2A[0][ng][3] = pack_h2(fast_gelu(c0[6] + b2v), fast_gelu(c0[7] + b3v));
            h2A[1][ng][0] = pack_h2(fast_gelu(c1[0] + b0), fast_gelu(c1[1] + b1v));
            h2A[1][ng][1] = pack_h2(fast_gelu(c1[2] + b0), fast_gelu(c1[3] + b1v));
            h2A[1][ng][2] = pack_h2(fast_gelu(c1[4] + b2v), fast_gelu(c1[5] + b3v));
            h2A[1][ng][3] = pack_h2(fast_gelu(c1[6] + b2v), fast_gelu(c1[7] + b3v));
        }
    }

    __syncthreads();     // all warps done with bufA
    copy_w_async(g_Wh + 65536, 256, 128, bufA, 136, tid);  // group: W4a
    cp_commit();
    cp_wait<1>();        // W3 ready (W4a still in flight)
    __syncthreads();

    // ---- layer 3: h2[2][16x256] @ W3[128x256]^T -> h3 fragments ----
    uint32_t h3A[2][8][4];
    {
        uint32_t wb = bufB + (uint32_t)((wrow * 264 + wcol) * 2);
#pragma unroll
        for (int ng = 0; ng < 8; ++ng) {
            int n0 = ng * 16;
            float c0[8] = {0, 0, 0, 0, 0, 0, 0, 0};
            float c1[8] = {0, 0, 0, 0, 0, 0, 0, 0};
#pragma unroll
            for (int kt = 0; kt < 16; ++kt) {
                uint32_t bb[4];
                ldmatrix_x4(bb, wb + (uint32_t)(n0 * 528 + kt * 32));
                mma16816(c0 + 0, h2A[0][kt], bb[0], bb[2]);
                mma16816(c0 + 4, h2A[0][kt], bb[1], bb[3]);
                mma16816(c1 + 0, h2A[1][kt], bb[0], bb[2]);
                mma16816(c1 + 4, h2A[1][kt], bb[1], bb[3]);
            }
            float b0 = sB3[n0 + 2 * t], b1v = sB3[n0 + 2 * t + 1];
            float b2v = sB3[n0 + 8 + 2 * t], b3v = sB3[n0 + 9 + 2 * t];
            h3A[0][ng][0] = pack_h2(fast_gelu(c0[0] + b0), fast_gelu(c0[1] + b1v));
            h3A[0][ng][1] = pack_h2(fast_gelu(c0[2] + b0), fast_gelu(c0[3] + b1v));
            h3A[0][ng][2] = pack_h2(fast_gelu(c0[4] + b2v), fast_gelu(c0[5] + b3v));
            h3A[0][ng][3] = pack_h2(fast_gelu(c0[6] + b2v), fast_gelu(c0[7] + b3v));
            h3A[1][ng][0] = pack_h2(fast_gelu(c1[0] + b0), fast_gelu(c1[1] + b1v));
            h3A[1][ng][1] = pack_h2(fast_gelu(c1[2] + b0), fast_gelu(c1[3] + b1v));
            h3A[1][ng][2] = pack_h2(fast_gelu(c1[4] + b2v), fast_gelu(c1[5] + b3v));
            h3A[1][ng][3] = pack_h2(fast_gelu(c1[6] + b2v), fast_gelu(c1[7] + b3v));
        }
    }

    __syncthreads();     // all warps done with bufB
    copy_w_async(g_Wh + 65536 + 32768, 256, 128, bufB, 136, tid);  // group: W4b
    cp_commit();
    cp_wait<1>();        // W4a ready (W4b still in flight)
    __syncthreads();

#pragma unroll
    for (int half = 0; half < 2; ++half) {
        uint32_t wb = (half == 0 ? bufA : bufB) + (uint32_t)((wrow * 136 + wcol) * 2);
        int base_n = half * 256;
#pragma unroll
        for (int ng = 0; ng < 16; ++ng) {
            int n0 = ng * 16;
            float c0[8] = {0, 0, 0, 0, 0, 0, 0, 0};
            float c1[8] = {0, 0, 0, 0, 0, 0, 0, 0};
#pragma unroll
            for (int kt = 0; kt < 8; ++kt) {
                uint32_t bb[4];
                ldmatrix_x4(bb, wb + (uint32_t)(n0 * 272 + kt * 32));
                mma16816(c0 + 0, h3A[0][kt], bb[0], bb[2]);
                mma16816(c0 + 4, h3A[0][kt], bb[1], bb[3]);
                mma16816(c1 + 0, h3A[1][kt], bb[0], bb[2]);
                mma16816(c1 + 4, h3A[1][kt], bb[1], bb[3]);
            }
            int cc0 = base_n + n0 + 2 * t;
            int cc1 = base_n + n0 + 8 + 2 * t;
#pragma unroll
            for (int s = 0; s < 2; ++s) {
                const float* cs = (s == 0) ? c0 : c1;
#pragma unroll
                for (int h = 0; h < 2; ++h) {
                    int row = s * 128 + r0 + g + h * 8;
                    int p   = sPad[row];
                    int tk  = p ? 0 : sTok[row];
                    const float* e0 = emb + tk * 512;
                    float* o0 = out + (size_t)(R0 + row) * 512;
                    float2 e, o;
                    e = *(const float2*)(e0 + cc0);
                    o.x = p ? e.x : (cs[h * 2 + 0] + e.x);
                    o.y = p ? e.y : (cs[h * 2 + 1] + e.y);
                    *(float2*)(o0 + cc0) = o;
                    e = *(const float2*)(e0 + cc1);
                    o.x = p ? e.x : (cs[h * 2 + 4] + e.x);
                    o.y = p ? e.y : (cs[h * 2 + 5] + e.y);
                    *(float2*)(o0 + cc1) = o;
                }
            }
        }
        if (half == 0) {
            cp_wait<0>();    // W4b ready
            __syncthreads();
        }
    }
}

extern "C" void kernel_launch(void* const* d_in, const int* in_sizes, int n_in,
                              void* d_out, int out_size) {
    const float* joint_info  = (const float*)d_in[0];
    const int*   joint_token = (const int*)d_in[1];
    const float* emb         = (const float*)d_in[2];
    const float* W1          = (const float*)d_in[3];
    const float* b1          = (const float*)d_in[4];
    const float* W2          = (const float*)d_in[5];
    const float* b2          = (const float*)d_in[6];
    const float* W3          = (const float*)d_in[7];
    const float* b3          = (const float*)d_in[8];
    const float* W4          = (const float*)d_in[9];

    cvt_weights_kernel<<<256, 256>>>(W2, W3, W4);

    cudaFuncSetAttribute(embedder_kernel,
                         cudaFuncAttributeMaxDynamicSharedMemorySize, SMEM_BYTES);
    embedder_kernel<<<N_ROWS / TILE_M, NTHREADS, SMEM_BYTES>>>(
        joint_info, joint_token, emb, W1, b1, b2, b3, (float*)d_out);
}

// round 8
// speedup vs baseline: 1.9973x; 1.9973x over previous
#include <cuda_runtime.h>
#include <cuda_fp16.h>
#include <stdint.h>

#define N_ROWS   262144
#define TILE_M   64
#define NTHREADS 128
#define SMEM_BYTES 110080

// fp16 weights: W2 [256][128] @0, W3 [128][256] @32768, W4 [512][128] @65536
__device__ __half g_Wh[131072];

__global__ void cvt_weights_kernel(const float* __restrict__ W2,
                                   const float* __restrict__ W3,
                                   const float* __restrict__ W4) {
    int i = blockIdx.x * blockDim.x + threadIdx.x;   // 65536 threads
    if (i < 32768) {
        g_Wh[i]         = __float2half_rn(W2[i]);
        g_Wh[32768 + i] = __float2half_rn(W3[i]);
    }
    g_Wh[65536 + i] = __float2half_rn(W4[i]);
}

__device__ __forceinline__ uint32_t smem_u32(const void* p) {
    return (uint32_t)__cvta_generic_to_shared(p);
}

__device__ __forceinline__ void ldmatrix_x4(uint32_t r[4], uint32_t addr) {
    asm volatile("ldmatrix.sync.aligned.m8n8.x4.shared.b16 {%0,%1,%2,%3}, [%4];\n"
                 : "=r"(r[0]), "=r"(r[1]), "=r"(r[2]), "=r"(r[3]) : "r"(addr));
}

__device__ __forceinline__ void mma16816(float c[4], const uint32_t a[4], uint32_t b0, uint32_t b1) {
    asm volatile("mma.sync.aligned.m16n8k16.row.col.f32.f16.f16.f32 "
                 "{%0,%1,%2,%3},{%4,%5,%6,%7},{%8,%9},{%0,%1,%2,%3};\n"
                 : "+f"(c[0]), "+f"(c[1]), "+f"(c[2]), "+f"(c[3])
                 : "r"(a[0]), "r"(a[1]), "r"(a[2]), "r"(a[3]), "r"(b0), "r"(b1));
}

__device__ __forceinline__ void cp_async16(uint32_t dst_smem, const void* src) {
    asm volatile("cp.async.cg.shared.global [%0], [%1], 16;\n" :: "r"(dst_smem), "l"(src));
}
__device__ __forceinline__ void cp_commit() { asm volatile("cp.async.commit_group;\n"); }
template <int n>
__device__ __forceinline__ void cp_wait() { asm volatile("cp.async.wait_group %0;\n" :: "n"(n)); }

// tanh-GELU in sigmoid form: gelu(x) = x * sigmoid(1.5957691x + 0.0713548x^3)
__device__ __forceinline__ float fast_gelu(float x) {
    float x3 = x * x * x;
    float z  = fmaf(0.0713548162726f, x3, 1.5957691216057308f * x);
    float e  = __expf(-z);
    return __fdividef(x, 1.0f + e);
}

__device__ __forceinline__ uint32_t pack_h2(float a, float b) {
    __half2 h = __floats2half2_rn(a, b);
    return *(uint32_t*)&h;
}

// copy a 128x128 fp16 tile (src row stride src_ld halves) -> smem, dst stride 136 halves
__device__ __forceinline__ void copy_chunk(const __half* __restrict__ src, int src_ld,
                                           uint32_t dst, int tid) {
#pragma unroll
    for (int i = tid; i < 2048; i += NTHREADS) {
        int r = i >> 4, c = (i & 15) << 3;
        cp_async16(dst + (uint32_t)((r * 136 + c) * 2), src + r * src_ld + c);
    }
}

__global__ __launch_bounds__(NTHREADS, 2)
void embedder_kernel(const float* __restrict__ joint_info,
                     const int* __restrict__ joint_token,
                     const float* __restrict__ emb,
                     const float* __restrict__ W1, const float* __restrict__ b1,
                     const float* __restrict__ b2, const float* __restrict__ b3,
                     float* __restrict__ out) {
    extern __shared__ char smem[];
    // 3 weight buffers of 34816 B each (128 rows x 136 halves)
    float4* sX   = (float4*)(smem + 104448);     // 1024 B (64 rows)
    float*  sW1  = (float*)(smem + 105472);      // 2048 B
    float*  sB1  = (float*)(smem + 107520);      // 512 B
    float*  sB2  = (float*)(smem + 108032);      // 1024 B
    float*  sB3  = (float*)(smem + 109056);      // 512 B
    int*    sTok = (int*)(smem + 109568);        // 256 B
    int*    sPad = (int*)(smem + 109824);        // 256 B

    uint32_t buf0 = smem_u32(smem);
    uint32_t buf1 = buf0 + 34816;
    uint32_t buf2 = buf0 + 69632;

    int tid  = threadIdx.x;
    int lane = tid & 31, warp = tid >> 5;        // 4 warps
    int R0   = blockIdx.x * TILE_M;

    // ---- small data loads ----
    if (tid < 64) {
        float4 x = ((const float4*)joint_info)[R0 + tid];
        sX[tid]   = x;
        sTok[tid] = joint_token[R0 + tid];
        sPad[tid] = (x.x == 0.0f && x.y == 0.0f && x.z == 0.0f && x.w == 0.0f) ? 1 : 0;
    }
    sB1[tid] = b1[tid];
    sB3[tid] = b3[tid];
    sB2[tid] = b2[tid];  sB2[tid + 128] = b2[tid + 128];
    ((float2*)sW1)[tid] = ((const float2*)W1)[tid];
    ((float2*)sW1)[tid + 128] = ((const float2*)W1)[tid + 128];

    // ---- prefetch: c0=W2a->buf0, c1=W2b->buf1, c2=W3klo->buf2 ----
    copy_chunk(g_Wh,         128, buf0, tid);  cp_commit();   // G0
    copy_chunk(g_Wh + 16384, 128, buf1, tid);  cp_commit();   // G1
    copy_chunk(g_Wh + 32768, 256, buf2, tid);  cp_commit();   // G2
    __syncthreads();   // small data visible

    // per-lane fragment coords
    int g = lane >> 2, t = lane & 3;
    int mi = lane >> 3, ri = lane & 7;
    int wrow = ri + ((mi & 1) << 3);
    int wcol = (mi >> 1) << 3;
    int r0 = warp * 16;
    uint32_t wfix = (uint32_t)((wrow * 136 + wcol) * 2);

    // ---- layer 1 (K=4) scalar fp32 -> h1 A-fragments ----
    uint32_t h1A[8][4];
    {
        float4 xa = sX[r0 + g];
        float4 xb = sX[r0 + g + 8];
#pragma unroll
        for (int kt = 0; kt < 8; ++kt)
#pragma unroll
            for (int j = 0; j < 2; ++j) {
                int c0 = kt * 16 + j * 8 + t * 2;
                float4 w0 = *(const float4*)&sW1[c0 * 4];
                float4 w1 = *(const float4*)&sW1[(c0 + 1) * 4];
                float bb0 = sB1[c0], bb1 = sB1[c0 + 1];
                float ya0 = fmaf(xa.x, w0.x, fmaf(xa.y, w0.y, fmaf(xa.z, w0.z, fmaf(xa.w, w0.w, bb0))));
                float ya1 = fmaf(xa.x, w1.x, fmaf(xa.y, w1.y, fmaf(xa.z, w1.z, fmaf(xa.w, w1.w, bb1))));
                float yb0 = fmaf(xb.x, w0.x, fmaf(xb.y, w0.y, fmaf(xb.z, w0.z, fmaf(xb.w, w0.w, bb0))));
                float yb1 = fmaf(xb.x, w1.x, fmaf(xb.y, w1.y, fmaf(xb.z, w1.z, fmaf(xb.w, w1.w, bb1))));
                h1A[kt][2 * j + 0] = pack_h2(fast_gelu(ya0), fast_gelu(ya1));
                h1A[kt][2 * j + 1] = pack_h2(fast_gelu(yb0), fast_gelu(yb1));
            }
    }

    cp_wait<1>();        // G0,G1 done (W2 both halves)
    __syncthreads();

    // ---- layer 2: h1[16x128] @ W2[256x128]^T -> h2 fragments ----
    uint32_t h2A[16][4];
#pragma unroll
    for (int ng = 0; ng < 16; ++ng) {
        uint32_t wb = ((ng < 8) ? buf0 : buf1) + wfix;
        int n0 = (ng & 7) * 16;
        float c[8] = {0, 0, 0, 0, 0, 0, 0, 0};
#pragma unroll
        for (int kt = 0; kt < 8; ++kt) {
            uint32_t bb[4];
            ldmatrix_x4(bb, wb + (uint32_t)(n0 * 272 + kt * 32));
            mma16816(c + 0, h1A[kt], bb[0], bb[2]);
            mma16816(c + 4, h1A[kt], bb[1], bb[3]);
        }
        int nb = ng * 16;
        float b0 = sB2[nb + 2 * t], b1v = sB2[nb + 2 * t + 1];
        float b2v = sB2[nb + 8 + 2 * t], b3v = sB2[nb + 9 + 2 * t];
        h2A[ng][0] = pack_h2(fast_gelu(c[0] + b0), fast_gelu(c[1] + b1v));
        h2A[ng][1] = pack_h2(fast_gelu(c[2] + b0), fast_gelu(c[3] + b1v));
        h2A[ng][2] = pack_h2(fast_gelu(c[4] + b2v), fast_gelu(c[5] + b3v));
        h2A[ng][3] = pack_h2(fast_gelu(c[6] + b2v), fast_gelu(c[7] + b3v));
    }

    __syncthreads();     // done reading buf0/buf1
    copy_chunk(g_Wh + 32768 + 128, 256, buf0, tid);  cp_commit();  // G3: W3 khi
    copy_chunk(g_Wh + 65536,       128, buf1, tid);  cp_commit();  // G4: W4 q0
    cp_wait<1>();        // G2,G3 done (W3 both K-halves)
    __syncthreads();

    // ---- layer 3: h2[16x256] @ W3[128x256]^T (K split across buf2/buf0) ----
    uint32_t h3A[8][4];
#pragma unroll
    for (int ng = 0; ng < 8; ++ng) {
        int n0 = ng * 16;
        float c[8] = {0, 0, 0, 0, 0, 0, 0, 0};
#pragma unroll
        for (int kt = 0; kt < 16; ++kt) {
            uint32_t wb = ((kt < 8) ? buf2 : buf0) + wfix;
            uint32_t bb[4];
            ldmatrix_x4(bb, wb + (uint32_t)(n0 * 272 + (kt & 7) * 32));
            mma16816(c + 0, h2A[kt], bb[0], bb[2]);
            mma16816(c + 4, h2A[kt], bb[1], bb[3]);
        }
        float b0 = sB3[n0 + 2 * t], b1v = sB3[n0 + 2 * t + 1];
        float b2v = sB3[n0 + 8 + 2 * t], b3v = sB3[n0 + 9 + 2 * t];
        h3A[ng][0] = pack_h2(fast_gelu(c[0] + b0), fast_gelu(c[1] + b1v));
        h3A[ng][1] = pack_h2(fast_gelu(c[2] + b0), fast_gelu(c[3] + b1v));
        h3A[ng][2] = pack_h2(fast_gelu(c[4] + b2v), fast_gelu(c[5] + b3v));
        h3A[ng][3] = pack_h2(fast_gelu(c[6] + b2v), fast_gelu(c[7] + b3v));
    }

    __syncthreads();     // done reading buf2/buf0
    copy_chunk(g_Wh + 65536 + 16384, 128, buf2, tid);  cp_commit();  // G5: W4 q1
    copy_chunk(g_Wh + 65536 + 32768, 128, buf0, tid);  cp_commit();  // G6: W4 q2
    cp_wait<1>();        // G4,G5 done (W4 q0,q1)
    __syncthreads();

    // epilogue row constants
    int pa = sPad[r0 + g], pb = sPad[r0 + g + 8];
    int ta = pa ? 0 : sTok[r0 + g];
    int tb = pb ? 0 : sTok[r0 + g + 8];
    const float* ea = emb + ta * 512;
    const float* eb = emb + tb * 512;
    float* outa = out + (size_t)(R0 + r0 + g) * 512;
    float* outb = out + (size_t)(R0 + r0 + g + 8) * 512;

    // ---- layer 4, phase A: out cols [0,128) from buf1, [128,256) from buf2 ----
#pragma unroll
    for (int q = 0; q < 2; ++q) {
        uint32_t wb = ((q == 0) ? buf1 : buf2) + wfix;
        int base_n = q * 128;
#pragma unroll
        for (int ng = 0; ng < 8; ++ng) {
            int n0 = ng * 16;
            float c[8] = {0, 0, 0, 0, 0, 0, 0, 0};
#pragma unroll
            for (int kt = 0; kt < 8; ++kt) {
                uint32_t bb[4];
                ldmatrix_x4(bb, wb + (uint32_t)(n0 * 272 + kt * 32));
                mma16816(c + 0, h3A[kt], bb[0], bb[2]);
                mma16816(c + 4, h3A[kt], bb[1], bb[3]);
            }
            int cc0 = base_n + n0 + 2 * t;
            int cc1 = base_n + n0 + 8 + 2 * t;
            float2 e, o;
            e = *(const float2*)(ea + cc0);
            o.x = pa ? e.x : (c[0] + e.x);  o.y = pa ? e.y : (c[1] + e.y);
            *(float2*)(outa + cc0) = o;
            e = *(const float2*)(eb + cc0);
            o.x = pb ? e.x : (c[2] + e.x);  o.y = pb ? e.y : (c[3] + e.y);
            *(float2*)(outb + cc0) = o;
            e = *(const float2*)(ea + cc1);
            o.x = pa ? e.x : (c[4] + e.x);  o.y = pa ? e.y : (c[5] + e.y);
            *(float2*)(outa + cc1) = o;
            e = *(const float2*)(eb + cc1);
            o.x = pb ? e.x : (c[6] + e.x);  o.y = pb ? e.y : (c[7] + e.y);
            *(float2*)(outb + cc1) = o;
        }
    }

    __syncthreads();     // done reading buf1
    copy_chunk(g_Wh + 65536 + 49152, 128, buf1, tid);  cp_commit();  // G7: W4 q3
    cp_wait<0>();        // G6,G7 done
    __syncthreads();

    // ---- layer 4, phase B: out cols [256,384) from buf0, [384,512) from buf1 ----
#pragma unroll
    for (int q = 0; q < 2; ++q) {
        uint32_t wb = ((q == 0) ? buf0 : buf1) + wfix;
        int base_n = 256 + q * 128;
#pragma unroll
        for (int ng = 0; ng < 8; ++ng) {
            int n0 = ng * 16;
            float c[8] = {0, 0, 0, 0, 0, 0, 0, 0};
#pragma unroll
            for (int kt = 0; kt < 8; ++kt) {
                uint32_t bb[4];
                ldmatrix_x4(bb, wb + (uint32_t)(n0 * 272 + kt * 32));
                mma16816(c + 0, h3A[kt], bb[0], bb[2]);
                mma16816(c + 4, h3A[kt], bb[1], bb[3]);
            }
            int cc0 = base_n + n0 + 2 * t;
            int cc1 = base_n + n0 + 8 + 2 * t;
            float2 e, o;
            e = *(const float2*)(ea + cc0);
            o.x = pa ? e.x : (c[0] + e.x);  o.y = pa ? e.y : (c[1] + e.y);
            *(float2*)(outa + cc0) = o;
            e = *(const float2*)(eb + cc0);
            o.x = pb ? e.x : (c[2] + e.x);  o.y = pb ? e.y : (c[3] + e.y);
            *(float2*)(outb + cc0) = o;
            e = *(const float2*)(ea + cc1);
            o.x = pa ? e.x : (c[4] + e.x);  o.y = pa ? e.y : (c[5] + e.y);
            *(float2*)(outa + cc1) = o;
            e = *(const float2*)(eb + cc1);
            o.x = pb ? e.x : (c[6] + e.x);  o.y = pb ? e.y : (c[7] + e.y);
            *(float2*)(outb + cc1) = o;
        }
    }
}

extern "C" void kernel_launch(void* const* d_in, const int* in_sizes, int n_in,
                              void* d_out, int out_size) {
    const float* joint_info  = (const float*)d_in[0];
    const int*   joint_token = (const int*)d_in[1];
    const float* emb         = (const float*)d_in[2];
    const float* W1          = (const float*)d_in[3];
    const float* b1          = (const float*)d_in[4];
    const float* W2          = (const float*)d_in[5];
    const float* b2          = (const float*)d_in[6];
    const float* W3          = (const float*)d_in[7];
    const float* b3          = (const float*)d_in[8];
    const float* W4          = (const float*)d_in[9];

    cvt_weights_kernel<<<256, 256>>>(W2, W3, W4);

    cudaFuncSetAttribute(embedder_kernel,
                         cudaFuncAttributeMaxDynamicSharedMemorySize, SMEM_BYTES);
    embedder_kernel<<<N_ROWS / TILE_M, NTHREADS, SMEM_BYTES>>>(
        joint_info, joint_token, emb, W1, b1, b2, b3, (float*)d_out);
}